// round 4
// baseline (speedup 1.0000x reference)
#include <cuda_runtime.h>
#include <math.h>

// ---------------------------------------------------------------------------
// TrLaplacianDP: out = embs + noise, where noise[0:300] are the first 300
// accepted samples of a truncated-Laplacian rejection scan over (sgn, u).
//
// R4: ONE fused kernel. Every block redundantly computes the noise vector
// into shared memory (sgn/u prefix is ~21KB, L2-resident; 4096 samples in
// one chunk covers the expected ~2600 needed), then streams its slice of
// the 314MB broadcast-add. Eliminates the second launch and the single-SM
// serialized noise kernel entirely.
// ---------------------------------------------------------------------------

#define EMBS_DIM 300
#define BLK      1024
#define GRID     600
#define IT       16
#define STRIDE   (GRID * BLK)          // 614400 = 75 * 8192
#define CHUNK    (BLK * 4)             // 4096 samples per scan chunk

// ---------------------------------------------------------------------------
// Shared noise scan: first 300 accepted r values -> s_noise[0..299].
// Sample i is handled by thread i/4 (float4 layout preserves order).
// ---------------------------------------------------------------------------
__device__ __forceinline__ void scan_noise(const float* __restrict__ sgn,
                                           const float* __restrict__ u,
                                           int n, float* s_noise,
                                           int* s_wsum, int* s_misc) {
    const double SCALE_D = 2.0 * 0.005 * sqrt(300.0) / 1.0;
    const float  SCALE_F = (float)SCALE_D;
    const float  A_F     = (float)(-SCALE_D * log(1.0 - 2.0 * 1.0 / sqrt(300.0)));

    const int tid  = threadIdx.x;
    const int lane = tid & 31;
    const int wid  = tid >> 5;
    int& s_carry = s_misc[0];
    int& s_total = s_misc[1];

    if (tid < 304) s_noise[tid] = 0.0f;
    if (tid == 0) s_carry = 0;
    __syncthreads();

    for (int base = 0; base < n; base += CHUNK) {
        const int i0 = base + tid * 4;
        float r[4];
        bool  m[4];
        float sv[4], uv[4];
        bool have[4];

        if (i0 + 3 < n) {
            const float4 s4 = *reinterpret_cast<const float4*>(sgn + i0);
            const float4 u4 = *reinterpret_cast<const float4*>(u + i0);
            sv[0]=s4.x; sv[1]=s4.y; sv[2]=s4.z; sv[3]=s4.w;
            uv[0]=u4.x; uv[1]=u4.y; uv[2]=u4.z; uv[3]=u4.w;
            have[0]=have[1]=have[2]=have[3]=true;
        } else {
            #pragma unroll
            for (int j = 0; j < 4; ++j) {
                const int i = i0 + j;
                have[j] = (i < n);
                sv[j] = have[j] ? sgn[i] : 0.0f;
                uv[j] = have[j] ? u[i]   : 1.0f;
            }
        }

        int cnt = 0;
        #pragma unroll
        for (int j = 0; j < 4; ++j) {
            const float s = (sv[j] > 0.0f) ? 1.0f : ((sv[j] < 0.0f) ? -1.0f : 0.0f);
            r[j] = (-SCALE_F * s) * logf(uv[j]);
            // Boundary band: double-precision recompute so acceptance and
            // stored values match fp32-reference semantics exactly there.
            if (fabsf(fabsf(r[j]) - A_F) < 1e-4f)
                r[j] = (-SCALE_F * s) * (float)log((double)uv[j]);
            m[j] = have[j] && (r[j] >= -A_F) && (r[j] <= A_F);
            cnt += m[j] ? 1 : 0;
        }

        // Warp inclusive scan of per-thread counts.
        int incl = cnt;
        #pragma unroll
        for (int o = 1; o < 32; o <<= 1) {
            const int v = __shfl_up_sync(0xffffffffu, incl, o);
            if (lane >= o) incl += v;
        }
        if (lane == 31) s_wsum[wid] = incl;
        __syncthreads();

        // Warp 0 scans the 32 warp totals.
        if (wid == 0) {
            const int v = s_wsum[lane];
            int iv = v;
            #pragma unroll
            for (int o = 1; o < 32; o <<= 1) {
                const int x = __shfl_up_sync(0xffffffffu, iv, o);
                if (lane >= o) iv += x;
            }
            s_wsum[lane] = iv - v;              // exclusive warp offset
            if (lane == 31) s_total = iv;       // chunk total
        }
        __syncthreads();

        int pos = s_carry + s_wsum[wid] + (incl - cnt);
        #pragma unroll
        for (int j = 0; j < 4; ++j) {
            if (m[j]) {
                if (pos < EMBS_DIM) s_noise[pos] = r[j];
                ++pos;
            }
        }
        __syncthreads();
        if (tid == 0) s_carry += s_total;
        __syncthreads();
        if (s_carry >= EMBS_DIM) break;          // uniform
    }
    __syncthreads();
}

// ---------------------------------------------------------------------------
// Fused kernel (exact shape): noise scan in smem, then unpredicated
// float4 streaming add with loop-invariant noise registers.
// ---------------------------------------------------------------------------
__global__ void __launch_bounds__(BLK, 2) fused_kernel(
        const float* __restrict__ embs,
        const float* __restrict__ sgn,
        const float* __restrict__ u,
        float* __restrict__ out, int nsamp) {
    __shared__ __align__(16) float s_noise[304];   // 75 float4 + pad
    __shared__ int s_wsum[32];
    __shared__ int s_misc[2];

    scan_noise(sgn, u, nsamp, s_noise, s_wsum, s_misc);

    const float4* __restrict__ in4  = reinterpret_cast<const float4*>(embs);
    float4* __restrict__       out4 = reinterpret_cast<float4*>(out);
    const float4* s_noise4 = reinterpret_cast<const float4*>(s_noise);

    const int v0    = blockIdx.x * BLK + threadIdx.x;
    const float4 nz = s_noise4[v0 % 75];   // STRIDE % 75 == 0 -> invariant

    #pragma unroll
    for (int k = 0; k < IT; ++k) {
        const int vi = v0 + k * STRIDE;
        float4 e = __ldcs(&in4[vi]);
        e.x += nz.x; e.y += nz.y; e.z += nz.z; e.w += nz.w;
        __stcs(&out4[vi], e);
    }
}

// ---------------------------------------------------------------------------
// General fallback (any shape): same fused structure, grid-stride + tail.
// ---------------------------------------------------------------------------
__global__ void __launch_bounds__(BLK, 2) fused_general_kernel(
        const float* __restrict__ embs,
        const float* __restrict__ sgn,
        const float* __restrict__ u,
        float* __restrict__ out, int nsamp, int n4, int n) {
    __shared__ __align__(16) float s_noise[304];
    __shared__ int s_wsum[32];
    __shared__ int s_misc[2];

    scan_noise(sgn, u, nsamp, s_noise, s_wsum, s_misc);

    const float4* __restrict__ in4  = reinterpret_cast<const float4*>(embs);
    float4* __restrict__       out4 = reinterpret_cast<float4*>(out);
    const float4* s_noise4 = reinterpret_cast<const float4*>(s_noise);

    const int stride = gridDim.x * BLK;            // multiple of 75
    const int v0     = blockIdx.x * BLK + threadIdx.x;
    const float4 nz  = s_noise4[v0 % 75];

    for (int v = v0; v < n4; v += 8 * stride) {
        #pragma unroll
        for (int k = 0; k < 8; ++k) {
            const int vi = v + k * stride;
            if (vi < n4) {
                float4 e = __ldcs(&in4[vi]);
                e.x += nz.x; e.y += nz.y; e.z += nz.z; e.w += nz.w;
                __stcs(&out4[vi], e);
            }
        }
    }
    const int tail_start = n4 * 4;
    for (int i = tail_start + v0; i < n; i += stride)
        out[i] = embs[i] + s_noise[i % EMBS_DIM];
}

// ---------------------------------------------------------------------------
extern "C" void kernel_launch(void* const* d_in, const int* in_sizes, int n_in,
                              void* d_out, int out_size) {
    const float* embs = (const float*)d_in[0];
    const float* sgn  = (const float*)d_in[1];
    const float* u    = (const float*)d_in[2];
    float* out        = (float*)d_out;

    const int nsamp = in_sizes[1];
    const int n  = out_size;
    const int n4 = n / 4;

    if (n == n4 * 4 && n4 == GRID * BLK * IT) {
        fused_kernel<<<GRID, BLK>>>(embs, sgn, u, out, nsamp);
    } else {
        int grid = (n4 + BLK * 8 - 1) / (BLK * 8);
        grid = ((grid + 74) / 75) * 75;            // stride % 75 == 0
        if (grid < 75) grid = 75;
        fused_general_kernel<<<grid, BLK>>>(embs, sgn, u, out, nsamp, n4, n);
    }
}

// round 5
// speedup vs baseline: 1.2796x; 1.2796x over previous
#include <cuda_runtime.h>
#include <math.h>

// ---------------------------------------------------------------------------
// TrLaplacianDP: out = embs + noise, where noise[0:300] are the first 300
// accepted samples of a truncated-Laplacian rejection scan over (sgn, u).
//
// R5: fused single kernel (R4 structure), but the per-block redundant scan
// uses a LOG-FREE mask:  |r| <= A  <=>  u >= 1 - 2/sqrt(300)  (exact
// analytic inversion). logf is computed lazily only for accepted samples
// with pos < 300 (~300 per block instead of 4096). A +-2e-5 band around
// the u-threshold (plus sgn==0) falls back to the exact R3 log path, so
// boundary decisions match the previously-passing kernel bit-for-bit.
// ---------------------------------------------------------------------------

#define EMBS_DIM 300
#define BLK      1024
#define GRID     600
#define IT       16
#define STRIDE   (GRID * BLK)          // 614400 = 75 * 8192
#define CHUNK    (BLK * 4)             // 4096 samples per scan chunk

__device__ __forceinline__ float sign_of(float x) {
    return (x > 0.0f) ? 1.0f : ((x < 0.0f) ? -1.0f : 0.0f);
}

// ---------------------------------------------------------------------------
// Shared noise scan: first 300 accepted r values -> s_noise[0..299].
// Sample i handled by thread i/4 (float4 layout preserves order).
// ---------------------------------------------------------------------------
__device__ __forceinline__ void scan_noise(const float* __restrict__ sgn,
                                           const float* __restrict__ u,
                                           int n, float* s_noise,
                                           int* s_wsum, int* s_misc) {
    const double SCALE_D = 2.0 * 0.005 * sqrt(300.0) / 1.0;
    const float  SCALE_F = (float)SCALE_D;
    const float  A_F     = (float)(-SCALE_D * log(1.0 - 2.0 * 1.0 / sqrt(300.0)));
    const float  U_THR   = (float)(1.0 - 2.0 / sqrt(300.0));   // exp(-A/SCALE)
    const float  BAND    = 2e-5f;

    const int tid  = threadIdx.x;
    const int lane = tid & 31;
    const int wid  = tid >> 5;
    int& s_carry = s_misc[0];
    int& s_total = s_misc[1];

    if (tid < 304) s_noise[tid] = 0.0f;
    if (tid == 0) s_carry = 0;
    __syncthreads();

    for (int base = 0; base < n; base += CHUNK) {
        const int i0 = base + tid * 4;
        float sv[4], uv[4];
        bool  have[4], m[4], rdone[4];
        float rv[4];

        if (i0 + 3 < n) {
            const float4 s4 = *reinterpret_cast<const float4*>(sgn + i0);
            const float4 u4 = *reinterpret_cast<const float4*>(u + i0);
            sv[0]=s4.x; sv[1]=s4.y; sv[2]=s4.z; sv[3]=s4.w;
            uv[0]=u4.x; uv[1]=u4.y; uv[2]=u4.z; uv[3]=u4.w;
            have[0]=have[1]=have[2]=have[3]=true;
        } else {
            #pragma unroll
            for (int j = 0; j < 4; ++j) {
                const int i = i0 + j;
                have[j] = (i < n);
                sv[j] = have[j] ? sgn[i] : 0.0f;
                uv[j] = have[j] ? u[i]   : 0.0f;   // u=0 -> fast reject
            }
        }

        int cnt = 0;
        #pragma unroll
        for (int j = 0; j < 4; ++j) {
            rdone[j] = false;
            rv[j] = 0.0f;
            if (fabsf(uv[j] - U_THR) < BAND || sv[j] == 0.0f) {
                // Exact path (rare): same semantics as the passing R3 kernel.
                const float s = sign_of(sv[j]);
                float r = (-SCALE_F * s) * logf(uv[j]);
                if (fabsf(fabsf(r) - A_F) < 1e-4f)
                    r = (-SCALE_F * s) * (float)log((double)uv[j]);
                m[j] = have[j] && (r >= -A_F) && (r <= A_F);
                rv[j] = r; rdone[j] = true;
            } else {
                m[j] = have[j] && (uv[j] >= U_THR);   // log-free mask
            }
            cnt += m[j] ? 1 : 0;
        }

        // Warp inclusive scan of per-thread counts.
        int incl = cnt;
        #pragma unroll
        for (int o = 1; o < 32; o <<= 1) {
            const int v = __shfl_up_sync(0xffffffffu, incl, o);
            if (lane >= o) incl += v;
        }
        if (lane == 31) s_wsum[wid] = incl;
        __syncthreads();

        // Warp 0 scans the 32 warp totals.
        if (wid == 0) {
            const int v = s_wsum[lane];
            int iv = v;
            #pragma unroll
            for (int o = 1; o < 32; o <<= 1) {
                const int x = __shfl_up_sync(0xffffffffu, iv, o);
                if (lane >= o) iv += x;
            }
            s_wsum[lane] = iv - v;              // exclusive warp offset
            if (lane == 31) s_total = iv;       // chunk total
        }
        __syncthreads();

        int pos = s_carry + s_wsum[wid] + (incl - cnt);
        #pragma unroll
        for (int j = 0; j < 4; ++j) {
            if (m[j]) {
                if (pos < EMBS_DIM) {
                    float r = rv[j];
                    if (!rdone[j])   // lazy logf: only ~300 per block
                        r = (-SCALE_F * sign_of(sv[j])) * logf(uv[j]);
                    s_noise[pos] = r;
                }
                ++pos;
            }
        }
        __syncthreads();
        if (tid == 0) s_carry += s_total;
        __syncthreads();
        if (s_carry >= EMBS_DIM) break;          // uniform
    }
    __syncthreads();
}

// ---------------------------------------------------------------------------
// Fused kernel (exact shape): smem noise scan, then unpredicated float4
// streaming add with loop-invariant noise registers.
// ---------------------------------------------------------------------------
__global__ void __launch_bounds__(BLK, 2) fused_kernel(
        const float* __restrict__ embs,
        const float* __restrict__ sgn,
        const float* __restrict__ u,
        float* __restrict__ out, int nsamp) {
    __shared__ __align__(16) float s_noise[304];   // 75 float4 + pad
    __shared__ int s_wsum[32];
    __shared__ int s_misc[2];

    scan_noise(sgn, u, nsamp, s_noise, s_wsum, s_misc);

    const float4* __restrict__ in4  = reinterpret_cast<const float4*>(embs);
    float4* __restrict__       out4 = reinterpret_cast<float4*>(out);
    const float4* s_noise4 = reinterpret_cast<const float4*>(s_noise);

    const int v0    = blockIdx.x * BLK + threadIdx.x;
    const float4 nz = s_noise4[v0 % 75];   // STRIDE % 75 == 0 -> invariant

    #pragma unroll
    for (int k = 0; k < IT; ++k) {
        const int vi = v0 + k * STRIDE;
        float4 e = __ldcs(&in4[vi]);
        e.x += nz.x; e.y += nz.y; e.z += nz.z; e.w += nz.w;
        __stcs(&out4[vi], e);
    }
}

// ---------------------------------------------------------------------------
// General fallback (any shape): same structure, grid-stride + tail.
// ---------------------------------------------------------------------------
__global__ void __launch_bounds__(BLK, 2) fused_general_kernel(
        const float* __restrict__ embs,
        const float* __restrict__ sgn,
        const float* __restrict__ u,
        float* __restrict__ out, int nsamp, int n4, int n) {
    __shared__ __align__(16) float s_noise[304];
    __shared__ int s_wsum[32];
    __shared__ int s_misc[2];

    scan_noise(sgn, u, nsamp, s_noise, s_wsum, s_misc);

    const float4* __restrict__ in4  = reinterpret_cast<const float4*>(embs);
    float4* __restrict__       out4 = reinterpret_cast<float4*>(out);
    const float4* s_noise4 = reinterpret_cast<const float4*>(s_noise);

    const int stride = gridDim.x * BLK;            // multiple of 75
    const int v0     = blockIdx.x * BLK + threadIdx.x;
    const float4 nz  = s_noise4[v0 % 75];

    for (int v = v0; v < n4; v += 8 * stride) {
        #pragma unroll
        for (int k = 0; k < 8; ++k) {
            const int vi = v + k * stride;
            if (vi < n4) {
                float4 e = __ldcs(&in4[vi]);
                e.x += nz.x; e.y += nz.y; e.z += nz.z; e.w += nz.w;
                __stcs(&out4[vi], e);
            }
        }
    }
    const int tail_start = n4 * 4;
    for (int i = tail_start + v0; i < n; i += stride)
        out[i] = embs[i] + s_noise[i % EMBS_DIM];
}

// ---------------------------------------------------------------------------
extern "C" void kernel_launch(void* const* d_in, const int* in_sizes, int n_in,
                              void* d_out, int out_size) {
    const float* embs = (const float*)d_in[0];
    const float* sgn  = (const float*)d_in[1];
    const float* u    = (const float*)d_in[2];
    float* out        = (float*)d_out;

    const int nsamp = in_sizes[1];
    const int n  = out_size;
    const int n4 = n / 4;

    if (n == n4 * 4 && n4 == GRID * BLK * IT) {
        fused_kernel<<<GRID, BLK>>>(embs, sgn, u, out, nsamp);
    } else {
        int grid = (n4 + BLK * 8 - 1) / (BLK * 8);
        grid = ((grid + 74) / 75) * 75;            // stride % 75 == 0
        if (grid < 75) grid = 75;
        fused_general_kernel<<<grid, BLK>>>(embs, sgn, u, out, nsamp, n4, n);
    }
}

// round 6
// speedup vs baseline: 1.4336x; 1.1204x over previous
#include <cuda_runtime.h>
#include <math.h>

// ---------------------------------------------------------------------------
// TrLaplacianDP: out = embs + noise, where noise[0:300] are the first 300
// accepted samples of a truncated-Laplacian rejection scan over (sgn, u).
//
// R6: two kernels again, but
//   - noise kernel uses the LOG-FREE mask  (|r|<=A  <=>  u >= 1-2/sqrt(300))
//     with lazy logf only for the ~300 stored values  -> ~2us on one block;
//   - add kernel launched with PDL (programmatic stream serialization) to
//     overlap its launch/prologue with the noise kernel; it calls
//     cudaGridDependencySynchronize() before reading g_noise.
// Boundary band (u within 2e-5 of threshold, or sgn==0) takes the exact
// logf + double-log path, matching the previously passing kernels.
// ---------------------------------------------------------------------------

#define EMBS_DIM 300
#define T_N      1024
#define NCHUNK   (T_N * 4)            // 4096 samples per scan chunk

#define ADD_GRID  4800
#define ADD_BLK   256
#define ADD_IT    8
#define ADD_STRIDE (ADD_GRID * ADD_BLK)   // 1228800 = 75 * 16384

__device__ __align__(16) float g_noise[304];   // 75 float4 + pad

__device__ __forceinline__ float sign_of(float x) {
    return (x > 0.0f) ? 1.0f : ((x < 0.0f) ? -1.0f : 0.0f);
}

// ---------------------------------------------------------------------------
// Kernel N: single-block ordered rejection scan, log-free mask.
// ---------------------------------------------------------------------------
__global__ void __launch_bounds__(T_N) noise_kernel(const float* __restrict__ sgn,
                                                    const float* __restrict__ u,
                                                    int n) {
    const double SCALE_D = 2.0 * 0.005 * sqrt(300.0) / 1.0;
    const float  SCALE_F = (float)SCALE_D;
    const float  A_F     = (float)(-SCALE_D * log(1.0 - 2.0 * 1.0 / sqrt(300.0)));
    const float  U_THR   = (float)(1.0 - 2.0 / sqrt(300.0));   // exp(-A/SCALE)
    const float  BAND    = 2e-5f;

    __shared__ int s_wsum[32];
    __shared__ int s_carry, s_total;

    const int tid  = threadIdx.x;
    const int lane = tid & 31;
    const int wid  = tid >> 5;

    if (tid < 304) g_noise[tid] = 0.0f;
    if (tid == 0) s_carry = 0;
    __syncthreads();

    for (int base = 0; base < n; base += NCHUNK) {
        const int i0 = base + tid * 4;
        float sv[4], uv[4];
        bool  have[4], m[4], rdone[4];
        float rv[4];

        if (i0 + 3 < n) {
            const float4 s4 = *reinterpret_cast<const float4*>(sgn + i0);
            const float4 u4 = *reinterpret_cast<const float4*>(u + i0);
            sv[0]=s4.x; sv[1]=s4.y; sv[2]=s4.z; sv[3]=s4.w;
            uv[0]=u4.x; uv[1]=u4.y; uv[2]=u4.z; uv[3]=u4.w;
            have[0]=have[1]=have[2]=have[3]=true;
        } else {
            #pragma unroll
            for (int j = 0; j < 4; ++j) {
                const int i = i0 + j;
                have[j] = (i < n);
                sv[j] = have[j] ? sgn[i] : 0.0f;
                uv[j] = have[j] ? u[i]   : 0.0f;   // u=0 -> fast reject
            }
        }

        int cnt = 0;
        #pragma unroll
        for (int j = 0; j < 4; ++j) {
            rdone[j] = false; rv[j] = 0.0f;
            if (fabsf(uv[j] - U_THR) < BAND || sv[j] == 0.0f) {
                // Exact path (rare): identical to previously-passing kernels.
                const float s = sign_of(sv[j]);
                float r = (-SCALE_F * s) * logf(uv[j]);
                if (fabsf(fabsf(r) - A_F) < 1e-4f)
                    r = (-SCALE_F * s) * (float)log((double)uv[j]);
                m[j] = have[j] && (r >= -A_F) && (r <= A_F);
                rv[j] = r; rdone[j] = true;
            } else {
                m[j] = have[j] && (uv[j] >= U_THR);   // log-free mask
            }
            cnt += m[j] ? 1 : 0;
        }

        // Warp inclusive scan of per-thread counts.
        int incl = cnt;
        #pragma unroll
        for (int o = 1; o < 32; o <<= 1) {
            const int v = __shfl_up_sync(0xffffffffu, incl, o);
            if (lane >= o) incl += v;
        }
        if (lane == 31) s_wsum[wid] = incl;
        __syncthreads();

        if (wid == 0) {
            const int v = s_wsum[lane];
            int iv = v;
            #pragma unroll
            for (int o = 1; o < 32; o <<= 1) {
                const int x = __shfl_up_sync(0xffffffffu, iv, o);
                if (lane >= o) iv += x;
            }
            s_wsum[lane] = iv - v;
            if (lane == 31) s_total = iv;
        }
        __syncthreads();

        int pos = s_carry + s_wsum[wid] + (incl - cnt);
        #pragma unroll
        for (int j = 0; j < 4; ++j) {
            if (m[j]) {
                if (pos < EMBS_DIM) {
                    float r = rv[j];
                    if (!rdone[j])   // lazy logf: ~300 total
                        r = (-SCALE_F * sign_of(sv[j])) * logf(uv[j]);
                    g_noise[pos] = r;
                }
                ++pos;
            }
        }
        __syncthreads();
        if (tid == 0) s_carry += s_total;
        __syncthreads();
        if (s_carry >= EMBS_DIM) break;          // uniform
    }
}

// ---------------------------------------------------------------------------
// Kernel B (exact fit): out = embs + broadcast(noise). PDL-aware.
// ---------------------------------------------------------------------------
__global__ void __launch_bounds__(ADD_BLK) add_exact_kernel(
        const float* __restrict__ embs, float* __restrict__ out) {
    // Wait for the noise kernel's g_noise writes (no-op without PDL).
    cudaGridDependencySynchronize();

    __shared__ float4 s_noise[75];
    if (threadIdx.x < 75)
        s_noise[threadIdx.x] = reinterpret_cast<const float4*>(g_noise)[threadIdx.x];
    __syncthreads();

    const float4* __restrict__ in4  = reinterpret_cast<const float4*>(embs);
    float4* __restrict__       out4 = reinterpret_cast<float4*>(out);

    const int v0    = blockIdx.x * ADD_BLK + threadIdx.x;
    const float4 nz = s_noise[v0 % 75];     // stride % 75 == 0 -> invariant

    #pragma unroll
    for (int k = 0; k < ADD_IT; ++k) {
        const int vi = v0 + k * ADD_STRIDE;
        float4 e = __ldcs(&in4[vi]);
        e.x += nz.x; e.y += nz.y; e.z += nz.z; e.w += nz.w;
        __stcs(&out4[vi], e);
    }
}

// ---------------------------------------------------------------------------
// Kernel B (general fallback): any shape. PDL-aware.
// ---------------------------------------------------------------------------
__global__ void __launch_bounds__(256) add_general_kernel(
        const float* __restrict__ embs, float* __restrict__ out,
        int n4, int n) {
    cudaGridDependencySynchronize();

    __shared__ float4 s_noise[75];
    if (threadIdx.x < 75)
        s_noise[threadIdx.x] = reinterpret_cast<const float4*>(g_noise)[threadIdx.x];
    __syncthreads();

    const float4* __restrict__ in4  = reinterpret_cast<const float4*>(embs);
    float4* __restrict__       out4 = reinterpret_cast<float4*>(out);

    const int stride = gridDim.x * blockDim.x;       // multiple of 75
    const int v0     = blockIdx.x * blockDim.x + threadIdx.x;
    const float4 nz  = s_noise[v0 % 75];

    for (int v = v0; v < n4; v += 8 * stride) {
        #pragma unroll
        for (int k = 0; k < 8; ++k) {
            const int vi = v + k * stride;
            if (vi < n4) {
                float4 e = __ldcs(&in4[vi]);
                e.x += nz.x; e.y += nz.y; e.z += nz.z; e.w += nz.w;
                __stcs(&out4[vi], e);
            }
        }
    }
    const int tail_start = n4 * 4;
    for (int i = tail_start + v0; i < n; i += stride)
        out[i] = embs[i] + g_noise[i % EMBS_DIM];
}

// ---------------------------------------------------------------------------
extern "C" void kernel_launch(void* const* d_in, const int* in_sizes, int n_in,
                              void* d_out, int out_size) {
    const float* embs = (const float*)d_in[0];
    const float* sgn  = (const float*)d_in[1];
    const float* u    = (const float*)d_in[2];
    float* out        = (float*)d_out;

    const int nsamp = in_sizes[1];
    noise_kernel<<<1, T_N>>>(sgn, u, nsamp);

    const int n  = out_size;
    const int n4 = n / 4;

    if (n == n4 * 4 && n4 == ADD_GRID * ADD_BLK * ADD_IT) {
        // PDL launch: overlap add-kernel launch with noise kernel; the
        // grid-dependency sync inside the kernel provides the ordering.
        cudaLaunchConfig_t cfg = {};
        cfg.gridDim  = dim3(ADD_GRID, 1, 1);
        cfg.blockDim = dim3(ADD_BLK, 1, 1);
        cudaLaunchAttribute attr[1];
        attr[0].id = cudaLaunchAttributeProgrammaticStreamSerialization;
        attr[0].val.programmaticStreamSerializationAllowed = 1;
        cfg.attrs = attr;
        cfg.numAttrs = 1;
        cudaError_t e = cudaLaunchKernelEx(&cfg, add_exact_kernel, embs, out);
        if (e != cudaSuccess) {
            (void)cudaGetLastError();               // clear sticky error
            add_exact_kernel<<<ADD_GRID, ADD_BLK>>>(embs, out);
        }
    } else {
        int grid = (n4 + 256 * 8 - 1) / (256 * 8);
        grid = ((grid + 74) / 75) * 75;             // stride % 75 == 0
        if (grid < 75) grid = 75;
        add_general_kernel<<<grid, 256>>>(embs, out, n4, n);
    }
}

// round 7
// speedup vs baseline: 1.4896x; 1.0390x over previous
#include <cuda_runtime.h>
#include <math.h>

// ---------------------------------------------------------------------------
// TrLaplacianDP: out = embs + noise, where noise[0:300] are the first 300
// accepted samples of a truncated-Laplacian rejection scan over (sgn, u).
//
// R7: PDL with real overlap. The add kernel PREFETCHES its 8 embs float4
// loads BEFORE cudaGridDependencySynchronize(), so wave-1 blocks stream
// embs from DRAM concurrently with the (1-block) noise kernel; the noise
// kernel's latency is hidden under the add kernel's own cold reads.
// Noise values are read post-sync as one L2-broadcast LDG.128 per thread
// (no smem stage, no extra barrier).
// ---------------------------------------------------------------------------

#define EMBS_DIM 300
#define T_N      1024
#define NCHUNK   (T_N * 4)            // 4096 samples per scan chunk

#define ADD_GRID  4800
#define ADD_BLK   256
#define ADD_IT    8
#define ADD_STRIDE (ADD_GRID * ADD_BLK)   // 1228800 = 75 * 16384

__device__ __align__(16) float g_noise[304];   // 75 float4 + pad

__device__ __forceinline__ float sign_of(float x) {
    return (x > 0.0f) ? 1.0f : ((x < 0.0f) ? -1.0f : 0.0f);
}

// ---------------------------------------------------------------------------
// Kernel N: single-block ordered rejection scan, log-free mask.
// |r| <= A  <=>  u >= 1 - 2/sqrt(300); logf only for stored values (~300).
// Boundary band (|u-thr|<2e-5 or sgn==0) uses the exact log path.
// ---------------------------------------------------------------------------
__global__ void __launch_bounds__(T_N) noise_kernel(const float* __restrict__ sgn,
                                                    const float* __restrict__ u,
                                                    int n) {
    const double SCALE_D = 2.0 * 0.005 * sqrt(300.0) / 1.0;
    const float  SCALE_F = (float)SCALE_D;
    const float  A_F     = (float)(-SCALE_D * log(1.0 - 2.0 * 1.0 / sqrt(300.0)));
    const float  U_THR   = (float)(1.0 - 2.0 / sqrt(300.0));   // exp(-A/SCALE)
    const float  BAND    = 2e-5f;

    __shared__ int s_wsum[32];
    __shared__ int s_carry, s_total;

    const int tid  = threadIdx.x;
    const int lane = tid & 31;
    const int wid  = tid >> 5;

    if (tid < 304) g_noise[tid] = 0.0f;
    if (tid == 0) s_carry = 0;
    __syncthreads();

    for (int base = 0; base < n; base += NCHUNK) {
        const int i0 = base + tid * 4;
        float sv[4], uv[4];
        bool  have[4], m[4], rdone[4];
        float rv[4];

        if (i0 + 3 < n) {
            const float4 s4 = *reinterpret_cast<const float4*>(sgn + i0);
            const float4 u4 = *reinterpret_cast<const float4*>(u + i0);
            sv[0]=s4.x; sv[1]=s4.y; sv[2]=s4.z; sv[3]=s4.w;
            uv[0]=u4.x; uv[1]=u4.y; uv[2]=u4.z; uv[3]=u4.w;
            have[0]=have[1]=have[2]=have[3]=true;
        } else {
            #pragma unroll
            for (int j = 0; j < 4; ++j) {
                const int i = i0 + j;
                have[j] = (i < n);
                sv[j] = have[j] ? sgn[i] : 0.0f;
                uv[j] = have[j] ? u[i]   : 0.0f;   // u=0 -> fast reject
            }
        }

        int cnt = 0;
        #pragma unroll
        for (int j = 0; j < 4; ++j) {
            rdone[j] = false; rv[j] = 0.0f;
            if (fabsf(uv[j] - U_THR) < BAND || sv[j] == 0.0f) {
                const float s = sign_of(sv[j]);
                float r = (-SCALE_F * s) * logf(uv[j]);
                if (fabsf(fabsf(r) - A_F) < 1e-4f)
                    r = (-SCALE_F * s) * (float)log((double)uv[j]);
                m[j] = have[j] && (r >= -A_F) && (r <= A_F);
                rv[j] = r; rdone[j] = true;
            } else {
                m[j] = have[j] && (uv[j] >= U_THR);   // log-free mask
            }
            cnt += m[j] ? 1 : 0;
        }

        int incl = cnt;
        #pragma unroll
        for (int o = 1; o < 32; o <<= 1) {
            const int v = __shfl_up_sync(0xffffffffu, incl, o);
            if (lane >= o) incl += v;
        }
        if (lane == 31) s_wsum[wid] = incl;
        __syncthreads();

        if (wid == 0) {
            const int v = s_wsum[lane];
            int iv = v;
            #pragma unroll
            for (int o = 1; o < 32; o <<= 1) {
                const int x = __shfl_up_sync(0xffffffffu, iv, o);
                if (lane >= o) iv += x;
            }
            s_wsum[lane] = iv - v;
            if (lane == 31) s_total = iv;
        }
        __syncthreads();

        int pos = s_carry + s_wsum[wid] + (incl - cnt);
        #pragma unroll
        for (int j = 0; j < 4; ++j) {
            if (m[j]) {
                if (pos < EMBS_DIM) {
                    float r = rv[j];
                    if (!rdone[j])
                        r = (-SCALE_F * sign_of(sv[j])) * logf(uv[j]);
                    g_noise[pos] = r;
                }
                ++pos;
            }
        }
        __syncthreads();
        if (tid == 0) s_carry += s_total;
        __syncthreads();
        if (s_carry >= EMBS_DIM) break;          // uniform
    }
}

// ---------------------------------------------------------------------------
// Kernel B (exact fit): prefetch embs BEFORE the PDL grid sync, then add.
// ---------------------------------------------------------------------------
__global__ void __launch_bounds__(ADD_BLK) add_exact_kernel(
        const float* __restrict__ embs, float* __restrict__ out) {
    const float4* __restrict__ in4  = reinterpret_cast<const float4*>(embs);
    float4* __restrict__       out4 = reinterpret_cast<float4*>(out);

    const int v0 = blockIdx.x * ADD_BLK + threadIdx.x;

    // ---- Pre-sync: independent embs reads overlap the noise kernel. ----
    float4 e[ADD_IT];
    #pragma unroll
    for (int k = 0; k < ADD_IT; ++k)
        e[k] = __ldcs(&in4[v0 + k * ADD_STRIDE]);

    // ---- Wait for noise kernel's g_noise writes (no-op without PDL). ----
    cudaGridDependencySynchronize();

    // One L2-broadcast LDG.128; invariant because ADD_STRIDE % 75 == 0.
    const float4 nz = reinterpret_cast<const float4*>(g_noise)[v0 % 75];

    #pragma unroll
    for (int k = 0; k < ADD_IT; ++k) {
        float4 t = e[k];
        t.x += nz.x; t.y += nz.y; t.z += nz.z; t.w += nz.w;
        __stcs(&out4[v0 + k * ADD_STRIDE], t);
    }
}

// ---------------------------------------------------------------------------
// Kernel B (general fallback): any shape. PDL-aware.
// ---------------------------------------------------------------------------
__global__ void __launch_bounds__(256) add_general_kernel(
        const float* __restrict__ embs, float* __restrict__ out,
        int n4, int n) {
    cudaGridDependencySynchronize();

    const float4* __restrict__ in4  = reinterpret_cast<const float4*>(embs);
    float4* __restrict__       out4 = reinterpret_cast<float4*>(out);

    const int stride = gridDim.x * blockDim.x;       // multiple of 75
    const int v0     = blockIdx.x * blockDim.x + threadIdx.x;
    const float4 nz  = reinterpret_cast<const float4*>(g_noise)[v0 % 75];

    for (int v = v0; v < n4; v += 8 * stride) {
        #pragma unroll
        for (int k = 0; k < 8; ++k) {
            const int vi = v + k * stride;
            if (vi < n4) {
                float4 t = __ldcs(&in4[vi]);
                t.x += nz.x; t.y += nz.y; t.z += nz.z; t.w += nz.w;
                __stcs(&out4[vi], t);
            }
        }
    }
    const int tail_start = n4 * 4;
    for (int i = tail_start + v0; i < n; i += stride)
        out[i] = embs[i] + g_noise[i % EMBS_DIM];
}

// ---------------------------------------------------------------------------
extern "C" void kernel_launch(void* const* d_in, const int* in_sizes, int n_in,
                              void* d_out, int out_size) {
    const float* embs = (const float*)d_in[0];
    const float* sgn  = (const float*)d_in[1];
    const float* u    = (const float*)d_in[2];
    float* out        = (float*)d_out;

    const int nsamp = in_sizes[1];
    noise_kernel<<<1, T_N>>>(sgn, u, nsamp);

    const int n  = out_size;
    const int n4 = n / 4;

    if (n == n4 * 4 && n4 == ADD_GRID * ADD_BLK * ADD_IT) {
        cudaLaunchConfig_t cfg = {};
        cfg.gridDim  = dim3(ADD_GRID, 1, 1);
        cfg.blockDim = dim3(ADD_BLK, 1, 1);
        cudaLaunchAttribute attr[1];
        attr[0].id = cudaLaunchAttributeProgrammaticStreamSerialization;
        attr[0].val.programmaticStreamSerializationAllowed = 1;
        cfg.attrs = attr;
        cfg.numAttrs = 1;
        cudaError_t e = cudaLaunchKernelEx(&cfg, add_exact_kernel, embs, out);
        if (e != cudaSuccess) {
            (void)cudaGetLastError();               // clear sticky error
            add_exact_kernel<<<ADD_GRID, ADD_BLK>>>(embs, out);
        }
    } else {
        int grid = (n4 + 256 * 8 - 1) / (256 * 8);
        grid = ((grid + 74) / 75) * 75;             // stride % 75 == 0
        if (grid < 75) grid = 75;
        add_general_kernel<<<grid, 256>>>(embs, out, n4, n);
    }
}